// round 2
// baseline (speedup 1.0000x reference)
#include <cuda_runtime.h>
#include <cuda_bf16.h>

// Problem constants (fixed by the reference)
#define NUM_TASKS 1000
#define N_FEAT    256
#define HID       128
#define BATCH_MAX 4096
#define RCMAX     8      // max rows per W1 streaming pass

// Scratch (static __device__ globals — allowed; no runtime allocation)
__device__ int g_offs[NUM_TASKS + 1];
__device__ int g_rows[BATCH_MAX];

// ---------------------------------------------------------------------------
// Setup: histogram task_ids -> scan -> scatter row indices (CSR).
// ---------------------------------------------------------------------------
__global__ __launch_bounds__(1024, 1)
void setup_kernel(const int* __restrict__ task_ids, int batch) {
    __shared__ int cnt[1024];
    __shared__ int scn[1024];

    int tid = threadIdx.x;
    cnt[tid] = 0;
    __syncthreads();

    for (int i = tid; i < batch; i += 1024)
        atomicAdd(&cnt[task_ids[i]], 1);
    __syncthreads();

    // inclusive Hillis-Steele scan over 1024 entries
    scn[tid] = cnt[tid];
    __syncthreads();
    #pragma unroll
    for (int off = 1; off < 1024; off <<= 1) {
        int self = scn[tid];
        int add  = (tid >= off) ? scn[tid - off] : 0;
        __syncthreads();
        scn[tid] = self + add;
        __syncthreads();
    }

    if (tid == 0) g_offs[0] = 0;
    if (tid < NUM_TASKS) g_offs[tid + 1] = scn[tid];

    int excl = scn[tid] - cnt[tid];
    __syncthreads();
    cnt[tid] = excl;
    __syncthreads();

    for (int i = tid; i < batch; i += 1024) {
        int t = task_ids[i];
        int pos = atomicAdd(&cnt[t], 1);
        g_rows[pos] = i;
    }
}

// ---------------------------------------------------------------------------
// One W1 streaming pass for R rows (R = 1,2,4,8 compile-time).
// tid in [0,128): q = tid&31 (h-quad), p = tid>>5 (f-phase warp).
// Iteration i: CTA reads contiguous 2KB stripe Wv[i*128 .. i*128+127].
// ---------------------------------------------------------------------------
template<int R>
__device__ __forceinline__
void stream_pass(const float4* __restrict__ Wv,
                 const float* __restrict__ x,
                 const float* __restrict__ b1s,
                 const float* __restrict__ w2s,
                 float b2,
                 float (*xs)[N_FEAT],          // [RCMAX][N_FEAT]
                 float (*red)[RCMAX][HID],     // [4][RCMAX][HID]
                 const int* __restrict__ rowp, // g_rows + start + r0
                 int nr,                        // actual rows (<= R)
                 float* __restrict__ out,
                 int tid, int q, int p) {
    // stage x rows into smem (zero-fill unused rows)
    #pragma unroll
    for (int r = 0; r < R; ++r) {
        float v0 = 0.f, v1 = 0.f;
        if (r < nr) {
            int row = rowp[r];
            v0 = x[(size_t)row * N_FEAT + tid];
            v1 = x[(size_t)row * N_FEAT + 128 + tid];
        }
        xs[r][tid]       = v0;
        xs[r][128 + tid] = v1;
    }
    __syncthreads();

    float4 acc[R];
    #pragma unroll
    for (int r = 0; r < R; ++r) acc[r] = make_float4(0.f, 0.f, 0.f, 0.f);

    // mainloop: stream 128KB of W1, fully coalesced float4
    #pragma unroll 4
    for (int i = 0; i < 64; ++i) {
        float4 w4 = Wv[i * 128 + tid];
        int f = i * 4 + p;
        #pragma unroll
        for (int r = 0; r < R; ++r) {
            float xv = xs[r][f];              // warp-uniform smem broadcast
            acc[r].x = fmaf(xv, w4.x, acc[r].x);
            acc[r].y = fmaf(xv, w4.y, acc[r].y);
            acc[r].z = fmaf(xv, w4.z, acc[r].z);
            acc[r].w = fmaf(xv, w4.w, acc[r].w);
        }
    }

    // cross-phase reduction staging
    #pragma unroll
    for (int r = 0; r < R; ++r)
        ((float4*)&red[p][r][0])[q] = acc[r];
    __syncthreads();

    // epilogue: warp p handles rows p, p+4, ...; lane q strides H by 32
    for (int rr = p; rr < nr; rr += 4) {
        float part = 0.f;
        #pragma unroll
        for (int hh = q; hh < HID; hh += 32) {
            float s = red[0][rr][hh] + red[1][rr][hh] +
                      red[2][rr][hh] + red[3][rr][hh] + b1s[hh];
            // exact-erf GELU
            float g = 0.5f * s * (1.0f + erff(s * 0.70710678118654752f));
            part = fmaf(g, w2s[hh], part);
        }
        #pragma unroll
        for (int off = 16; off > 0; off >>= 1)
            part += __shfl_down_sync(0xffffffffu, part, off);
        if (q == 0)
            out[rowp[rr]] = part + b2;
    }
    __syncthreads();   // protect xs/red for next pass
}

// ---------------------------------------------------------------------------
// Main: one CTA per task. Dispatch pass width on actual row count so we
// don't burn FMAs on zero-padded rows (mean rows/task ~4.1, RCMAX=8).
// ---------------------------------------------------------------------------
__global__ __launch_bounds__(128, 8)
void main_kernel(const float* __restrict__ x,
                 const float* __restrict__ l1_emb,
                 const float* __restrict__ l1_bias,
                 const float* __restrict__ l2_emb,
                 const float* __restrict__ l2_bias,
                 float* __restrict__ out) {
    int t = blockIdx.x;
    int start = g_offs[t];
    int n     = g_offs[t + 1] - start;
    if (n == 0) return;

    __shared__ float xs[RCMAX][N_FEAT];       // 8 KB
    __shared__ float red[4][RCMAX][HID];      // 16 KB
    __shared__ float b1s[HID], w2s[HID];

    int tid = threadIdx.x;
    int q = tid & 31;
    int p = tid >> 5;

    b1s[tid] = l1_bias[t * HID + tid];
    w2s[tid] = l2_emb[t * HID + tid];
    float b2 = l2_bias[t];

    const float4* __restrict__ Wv =
        (const float4*)(l1_emb + (size_t)t * (N_FEAT * HID));

    for (int r0 = 0; r0 < n; r0 += RCMAX) {
        int nr = min(RCMAX, n - r0);
        const int* rowp = g_rows + start + r0;
        if (nr <= 1)
            stream_pass<1>(Wv, x, b1s, w2s, b2, xs, red, rowp, nr, out, tid, q, p);
        else if (nr <= 2)
            stream_pass<2>(Wv, x, b1s, w2s, b2, xs, red, rowp, nr, out, tid, q, p);
        else if (nr <= 4)
            stream_pass<4>(Wv, x, b1s, w2s, b2, xs, red, rowp, nr, out, tid, q, p);
        else
            stream_pass<8>(Wv, x, b1s, w2s, b2, xs, red, rowp, nr, out, tid, q, p);
    }
}

extern "C" void kernel_launch(void* const* d_in, const int* in_sizes, int n_in,
                              void* d_out, int out_size) {
    const float* x        = (const float*)d_in[0];
    const int*   task_ids = (const int*)  d_in[1];
    const float* l1_emb   = (const float*)d_in[2];
    const float* l1_bias  = (const float*)d_in[3];
    const float* l2_emb   = (const float*)d_in[4];
    const float* l2_bias  = (const float*)d_in[5];
    float* out = (float*)d_out;

    int batch = in_sizes[1];   // 4096

    setup_kernel<<<1, 1024>>>(task_ids, batch);
    main_kernel<<<NUM_TASKS, 128>>>(x, l1_emb, l1_bias, l2_emb, l2_bias, out);
}

// round 3
// speedup vs baseline: 1.6440x; 1.6440x over previous
#include <cuda_runtime.h>
#include <cuda_bf16.h>

// Problem constants (fixed by the reference)
#define NUM_TASKS 1000
#define N_FEAT    256
#define HID       128
#define BATCH_MAX 4096
#define RCMAX     8      // max rows per W1 streaming pass

// Scratch (static __device__ globals — allowed; no runtime allocation)
__device__ int g_offs[NUM_TASKS + 1];
__device__ int g_rows[BATCH_MAX];
__device__ int g_order[NUM_TASKS];

// ---------------------------------------------------------------------------
// Setup: histogram task_ids -> scan -> scatter row indices (CSR), then
// counting-sort tasks by descending row count so long-running CTAs launch
// first (grid runs in ~2 waves; this shrinks the tail).
// ---------------------------------------------------------------------------
__global__ __launch_bounds__(1024, 1)
void setup_kernel(const int* __restrict__ task_ids, int batch) {
    __shared__ int cnt[1024];
    __shared__ int scn[1024];
    __shared__ int ccnt[32];
    __shared__ int ccur[32];

    int tid = threadIdx.x;
    cnt[tid] = 0;
    if (tid < 32) ccnt[tid] = 0;
    __syncthreads();

    for (int i = tid; i < batch; i += 1024)
        atomicAdd(&cnt[task_ids[i]], 1);
    __syncthreads();

    // inclusive Hillis-Steele scan over 1024 entries
    scn[tid] = cnt[tid];
    __syncthreads();
    #pragma unroll
    for (int off = 1; off < 1024; off <<= 1) {
        int self = scn[tid];
        int add  = (tid >= off) ? scn[tid - off] : 0;
        __syncthreads();
        scn[tid] = self + add;
        __syncthreads();
    }

    if (tid == 0) g_offs[0] = 0;
    if (tid < NUM_TASKS) g_offs[tid + 1] = scn[tid];

    int excl = scn[tid] - cnt[tid];
    __syncthreads();
    cnt[tid] = excl;
    __syncthreads();

    for (int i = tid; i < batch; i += 1024) {
        int t = task_ids[i];
        int pos = atomicAdd(&cnt[t], 1);
        g_rows[pos] = i;
    }

    // ---- counting sort of tasks by descending n (n clamped to 31) ----
    int n_t = 0, cls = 31;
    if (tid < NUM_TASKS) {
        n_t = scn[tid] - (tid ? scn[tid - 1] : 0);
        cls = 31 - min(n_t, 31);          // big n -> small class -> early bid
        atomicAdd(&ccnt[cls], 1);
    }
    __syncthreads();
    if (tid == 0) {
        int run = 0;
        #pragma unroll
        for (int c = 0; c < 32; ++c) { ccur[c] = run; run += ccnt[c]; }
    }
    __syncthreads();
    if (tid < NUM_TASKS) {
        int pos = atomicAdd(&ccur[cls], 1);
        g_order[pos] = tid;
    }
}

// ---------------------------------------------------------------------------
// One W1 streaming pass for R rows (R = 1,2,4,8 compile-time).
// tid in [0,128): q = tid&31 (h-quad), p = tid>>5 (f-phase warp).
// Mainloop is double-buffered: batch of 4 float4 prefetched while the
// previous batch feeds FMAs -> keeps >=4 LDG.128 in flight per thread.
// ---------------------------------------------------------------------------
template<int R>
__device__ __forceinline__
void stream_pass(const float4* __restrict__ Wv,
                 const float* __restrict__ x,
                 const float* __restrict__ b1s,
                 const float* __restrict__ w2s,
                 float b2,
                 float (*xs)[N_FEAT],
                 float (*red)[RCMAX][HID],
                 const int* __restrict__ rowp,
                 int nr,
                 float* __restrict__ out,
                 int tid, int q, int p) {
    // stage x rows into smem (zero-fill unused rows)
    #pragma unroll
    for (int r = 0; r < R; ++r) {
        float v0 = 0.f, v1 = 0.f;
        if (r < nr) {
            int row = rowp[r];
            v0 = x[(size_t)row * N_FEAT + tid];
            v1 = x[(size_t)row * N_FEAT + 128 + tid];
        }
        xs[r][tid]       = v0;
        xs[r][128 + tid] = v1;
    }
    __syncthreads();

    float4 acc[R];
    #pragma unroll
    for (int r = 0; r < R; ++r) acc[r] = make_float4(0.f, 0.f, 0.f, 0.f);

    // ---- pipelined mainloop: 16 batches of 4 iterations ----
    float4 buf[4];
    #pragma unroll
    for (int j = 0; j < 4; ++j) buf[j] = Wv[j * 128 + tid];

    #pragma unroll 2
    for (int ib = 0; ib < 16; ++ib) {
        float4 nbuf[4];
        if (ib < 15) {
            #pragma unroll
            for (int j = 0; j < 4; ++j)
                nbuf[j] = Wv[((ib + 1) * 4 + j) * 128 + tid];
        }
        #pragma unroll
        for (int j = 0; j < 4; ++j) {
            float4 w4 = buf[j];
            int f = (ib * 4 + j) * 4 + p;
            #pragma unroll
            for (int r = 0; r < R; ++r) {
                float xv = xs[r][f];          // warp-uniform smem broadcast
                acc[r].x = fmaf(xv, w4.x, acc[r].x);
                acc[r].y = fmaf(xv, w4.y, acc[r].y);
                acc[r].z = fmaf(xv, w4.z, acc[r].z);
                acc[r].w = fmaf(xv, w4.w, acc[r].w);
            }
        }
        #pragma unroll
        for (int j = 0; j < 4; ++j) buf[j] = nbuf[j];
    }

    // cross-phase reduction staging
    #pragma unroll
    for (int r = 0; r < R; ++r)
        ((float4*)&red[p][r][0])[q] = acc[r];
    __syncthreads();

    // epilogue: warp p handles rows p, p+4, ...; lane q strides H by 32
    for (int rr = p; rr < nr; rr += 4) {
        float part = 0.f;
        #pragma unroll
        for (int hh = q; hh < HID; hh += 32) {
            float s = red[0][rr][hh] + red[1][rr][hh] +
                      red[2][rr][hh] + red[3][rr][hh] + b1s[hh];
            // exact-erf GELU
            float g = 0.5f * s * (1.0f + erff(s * 0.70710678118654752f));
            part = fmaf(g, w2s[hh], part);
        }
        #pragma unroll
        for (int off = 16; off > 0; off >>= 1)
            part += __shfl_down_sync(0xffffffffu, part, off);
        if (q == 0)
            out[rowp[rr]] = part + b2;
    }
    __syncthreads();   // protect xs/red for next pass
}

// ---------------------------------------------------------------------------
// Main: one CTA per task (in descending-n launch order). Dispatch pass
// width on actual row count; regs relaxed to ~128 for load MLP.
// ---------------------------------------------------------------------------
__global__ __launch_bounds__(128, 4)
void main_kernel(const float* __restrict__ x,
                 const float* __restrict__ l1_emb,
                 const float* __restrict__ l1_bias,
                 const float* __restrict__ l2_emb,
                 const float* __restrict__ l2_bias,
                 float* __restrict__ out) {
    int t = g_order[blockIdx.x];
    int start = g_offs[t];
    int n     = g_offs[t + 1] - start;
    if (n == 0) return;

    __shared__ float xs[RCMAX][N_FEAT];       // 8 KB
    __shared__ float red[4][RCMAX][HID];      // 16 KB
    __shared__ float b1s[HID], w2s[HID];

    int tid = threadIdx.x;
    int q = tid & 31;
    int p = tid >> 5;

    b1s[tid] = l1_bias[t * HID + tid];
    w2s[tid] = l2_emb[t * HID + tid];
    float b2 = l2_bias[t];

    const float4* __restrict__ Wv =
        (const float4*)(l1_emb + (size_t)t * (N_FEAT * HID));

    for (int r0 = 0; r0 < n; r0 += RCMAX) {
        int nr = min(RCMAX, n - r0);
        const int* rowp = g_rows + start + r0;
        if (nr <= 1)
            stream_pass<1>(Wv, x, b1s, w2s, b2, xs, red, rowp, nr, out, tid, q, p);
        else if (nr <= 2)
            stream_pass<2>(Wv, x, b1s, w2s, b2, xs, red, rowp, nr, out, tid, q, p);
        else if (nr <= 4)
            stream_pass<4>(Wv, x, b1s, w2s, b2, xs, red, rowp, nr, out, tid, q, p);
        else
            stream_pass<8>(Wv, x, b1s, w2s, b2, xs, red, rowp, nr, out, tid, q, p);
    }
}

extern "C" void kernel_launch(void* const* d_in, const int* in_sizes, int n_in,
                              void* d_out, int out_size) {
    const float* x        = (const float*)d_in[0];
    const int*   task_ids = (const int*)  d_in[1];
    const float* l1_emb   = (const float*)d_in[2];
    const float* l1_bias  = (const float*)d_in[3];
    const float* l2_emb   = (const float*)d_in[4];
    const float* l2_bias  = (const float*)d_in[5];
    float* out = (float*)d_out;

    int batch = in_sizes[1];   // 4096

    setup_kernel<<<1, 1024>>>(task_ids, batch);
    main_kernel<<<NUM_TASKS, 128>>>(x, l1_emb, l1_bias, l2_emb, l2_bias, out);
}